// round 16
// baseline (speedup 1.0000x reference)
#include <cuda_runtime.h>
#include <cuda_bf16.h>

// ---------------- problem constants ----------------
#define BSZ   8
#define NC    128
#define TD    512
#define EDIM  64
#define NE    128
#define NTOK  (BSZ*NC)     // 1024 tokens
#define T2    (2*TD)       // 1024 concat dim

// ---------------- GEMM tiling ----------------
#define BN 128             // n-columns per CTA
#define NT (TD/BN)         // 4 n-tiles
#define KC 64              // k-tile
#define MC 32              // m rows per work item
#define NKT (TD/KC)        // 8 k-tiles
#define PITCH 36           // smem row pitch in u32 units (32 data + 4 pad)
#define APITCH 20          // proj kernel pitch (16 data u32 + 4 pad)
#define MAXW 256           // max work items

// ---------------- device scratch (no allocation allowed) ----------------
__device__ int   g_cnt[NE];
__device__ int   g_list[NE][NTOK];          // packed token*2 + slot
__device__ int   g_work[MAXW];              // expert | (m-slice << 16)
__device__ int   g_nwork;
__device__ float g_ps[NTOK][EDIM];          // router projections (256 KB)
__device__ float g_part[4][NTOK][TD];       // [slot*2+stream][token][t]  (8 MB)

// ---------------- helpers ----------------
__device__ __forceinline__ unsigned s2u(const void* p) {
    return (unsigned)__cvta_generic_to_shared(p);
}
__device__ __forceinline__ void ldsm4(unsigned* r, unsigned addr) {
    asm volatile("ldmatrix.sync.aligned.m8n8.x4.shared.b16 {%0,%1,%2,%3},[%4];"
                 : "=r"(r[0]), "=r"(r[1]), "=r"(r[2]), "=r"(r[3]) : "r"(addr));
}
__device__ __forceinline__ void mma16816(float* d, const unsigned* a, const unsigned* b) {
    asm volatile("mma.sync.aligned.m16n8k16.row.col.f32.bf16.bf16.f32 "
                 "{%0,%1,%2,%3},{%4,%5,%6,%7},{%8,%9},{%0,%1,%2,%3};"
                 : "+f"(d[0]), "+f"(d[1]), "+f"(d[2]), "+f"(d[3])
                 : "r"(a[0]), "r"(a[1]), "r"(a[2]), "r"(a[3]), "r"(b[0]), "r"(b[1]));
}
// split fp32 pair -> packed bf16x2 hi + lo (2-term expansion)
__device__ __forceinline__ void split2(float v0, float v1, unsigned& h, unsigned& l) {
    __nv_bfloat162 hb;
    hb.x = __float2bfloat16(v0);
    hb.y = __float2bfloat16(v1);
    h = *reinterpret_cast<unsigned*>(&hb);
    float r0 = v0 - __bfloat162float(hb.x);
    float r1 = v1 - __bfloat162float(hb.y);
    __nv_bfloat162 lb;
    lb.x = __float2bfloat16(r0);
    lb.y = __float2bfloat16(r1);
    l = *reinterpret_cast<unsigned*>(&lb);
}

// ---------------- kernel 0: zero per-expert counters ----------------
__global__ void zero_cnt_kernel() { g_cnt[threadIdx.x] = 0; }

// ---------------- kernel 1a: router projection as HMMA GEMM -------------
// g_ps[tok][j] = x_cat[tok] . projW[j] + projb[j], 8 CTAs x 128 tokens.
// 4-term bf16 split (hh+hl+lh+ll): score error ~1e-7 so the downstream
// top-2 decision cannot flip vs fp32.
__global__ __launch_bounds__(256) void proj_kernel(
    const float* __restrict__ x_l, const float* __restrict__ x_r,
    const float* __restrict__ projW, const float* __restrict__ projb)
{
    __shared__ unsigned Phi[64 * APITCH], Plo[64 * APITCH];    // 5.1 KB each
    __shared__ unsigned Ahi[128 * APITCH], Alo[128 * APITCH];  // 10.2 KB each

    int tid = threadIdx.x, lane = tid & 31, warp = tid >> 5;
    int tok0 = blockIdx.x * 128;

    // W loader: row = j (0..63), 2 float4 per thread
    int wrow = tid & 63;
    int wq   = (tid >> 6) * 2;        // float4 base 0,2,4,6
    // A loader: row = token (0..127), 4 float4 per thread
    int xrow = tid & 127;
    int xq   = (tid >> 7) * 4;        // float4 base 0 or 4

    float acc[8][4];
    #pragma unroll
    for (int q = 0; q < 8; ++q)
        #pragma unroll
        for (int i = 0; i < 4; ++i) acc[q][i] = 0.f;

    unsigned aOffU = (unsigned)((warp * 16 + (lane & 15)) * APITCH + ((lane >> 4) & 1) * 4);
    unsigned brow0 = (unsigned)(((lane >> 4) & 1) * 8 + (lane & 7));
    unsigned bkU   = (unsigned)(((lane >> 3) & 1) * 4);
    unsigned bOff[4];
    #pragma unroll
    for (int gg = 0; gg < 4; ++gg) bOff[gg] = (brow0 + 16 * gg) * APITCH + bkU;

    unsigned AhiA = s2u(Ahi), AloA = s2u(Alo), PhiA = s2u(Phi), PloA = s2u(Plo);

    for (int kt = 0; kt < 32; ++kt) {           // K=1024, 32 k-tiles of 32
        int k0 = kt * 32;
        __syncthreads();
        // ---- projW tile ----
        #pragma unroll
        for (int i = 0; i < 2; ++i) {
            int f4 = wq + i;
            float4 v = *reinterpret_cast<const float4*>(projW + (size_t)wrow * T2 + k0 + f4 * 4);
            unsigned h0, l0, h1, l1;
            split2(v.x, v.y, h0, l0);
            split2(v.z, v.w, h1, l1);
            int u = wrow * APITCH + f4 * 2;
            *reinterpret_cast<uint2*>(&Phi[u]) = make_uint2(h0, h1);
            *reinterpret_cast<uint2*>(&Plo[u]) = make_uint2(l0, l1);
        }
        // ---- x tile (concat: k<512 from x_l, else x_r) ----
        #pragma unroll
        for (int i = 0; i < 4; ++i) {
            int f4 = xq + i;
            int kg = k0 + f4 * 4;
            const float* src = (kg < TD) ? (x_l + (size_t)(tok0 + xrow) * TD + kg)
                                         : (x_r + (size_t)(tok0 + xrow) * TD + kg - TD);
            float4 v = *reinterpret_cast<const float4*>(src);
            unsigned h0, l0, h1, l1;
            split2(v.x, v.y, h0, l0);
            split2(v.z, v.w, h1, l1);
            int u = xrow * APITCH + f4 * 2;
            *reinterpret_cast<uint2*>(&Ahi[u]) = make_uint2(h0, h1);
            *reinterpret_cast<uint2*>(&Alo[u]) = make_uint2(l0, l1);
        }
        __syncthreads();
        // ---- 2 k16-chunks ----
        #pragma unroll
        for (int c = 0; c < 2; ++c) {
            unsigned cu4 = (unsigned)(c * 8) * 4u;
            unsigned ahi[4], alo[4], bh[4][4], bl[4][4];
            ldsm4(ahi, AhiA + aOffU * 4u + cu4);
            ldsm4(alo, AloA + aOffU * 4u + cu4);
            #pragma unroll
            for (int gg = 0; gg < 4; ++gg) {
                ldsm4(bh[gg], PhiA + bOff[gg] * 4u + cu4);
                ldsm4(bl[gg], PloA + bOff[gg] * 4u + cu4);
            }
            #pragma unroll
            for (int gg = 0; gg < 4; ++gg) {
                mma16816(acc[2 * gg],     ahi, bh[gg] + 0);
                mma16816(acc[2 * gg + 1], ahi, bh[gg] + 2);
                mma16816(acc[2 * gg],     ahi, bl[gg] + 0);
                mma16816(acc[2 * gg + 1], ahi, bl[gg] + 2);
                mma16816(acc[2 * gg],     alo, bh[gg] + 0);
                mma16816(acc[2 * gg + 1], alo, bh[gg] + 2);
                mma16816(acc[2 * gg],     alo, bl[gg] + 0);
                mma16816(acc[2 * gg + 1], alo, bl[gg] + 2);
            }
        }
    }

    // epilogue: rows warp*16 + (lane>>2) [+8], cols nt8*8 + (lane&3)*2
    int r0 = tok0 + warp * 16 + (lane >> 2);
    int c0 = (lane & 3) * 2;
    #pragma unroll
    for (int q = 0; q < 8; ++q) {
        int col = q * 8 + c0;
        float2 pb = *reinterpret_cast<const float2*>(projb + col);
        *reinterpret_cast<float2*>(&g_ps[r0][col]) =
            make_float2(acc[q][0] + pb.x, acc[q][1] + pb.y);
        *reinterpret_cast<float2*>(&g_ps[r0 + 8][col]) =
            make_float2(acc[q][2] + pb.x, acc[q][3] + pb.y);
    }
}

// ---------------- kernel 1b: scores + top-2 ----------------
// s_e = ps . centers[e]/||centers[e]||; x_proj L2-norm is a positive
// per-token scalar (order-preserving) and the reference's token-level mask
// makes each selected expert's combine weight exactly 1.0.
#define TPC 8
__global__ __launch_bounds__(256) void score_kernel(
    const float* __restrict__ centers)
{
    __shared__ float ps[TPC][EDIM];    // 2 KB
    __shared__ float ss[TPC][NE];      // 4 KB
    int tok0 = blockIdx.x * TPC;
    int tid = threadIdx.x;
    int warp = tid >> 5, lane = tid & 31;

    #pragma unroll
    for (int i = tid; i < TPC * EDIM; i += 256)
        ps[i >> 6][i & 63] = g_ps[tok0 + (i >> 6)][i & 63];
    __syncthreads();

    // 1024 (token, expert) scores over 256 threads, 4 rounds
    #pragma unroll
    for (int r = 0; r < 4; ++r) {
        int idx = tid + 256 * r;
        int t = idx >> 7, e = idx & 127;
        const float* c = centers + (size_t)e * EDIM;
        float s = 0.f, n = 0.f;
        #pragma unroll 8
        for (int j = 0; j < EDIM; ++j) { float cv = c[j]; s += ps[t][j] * cv; n += cv * cv; }
        ss[t][e] = s * rsqrtf(fmaxf(n, 1e-24f));
    }
    __syncthreads();

    // warp-parallel top-2: warp t reduces token t's 128 scores.
    // tie-break: smaller index wins (matches jax.lax.top_k first-index).
    {
        int t = warp;
        float v[4]; int id[4];
        #pragma unroll
        for (int q = 0; q < 4; ++q) { id[q] = lane + 32 * q; v[q] = ss[t][id[q]]; }
        float bv_ = v[0]; int bi = id[0];
        #pragma unroll
        for (int q = 1; q < 4; ++q)
            if (v[q] > bv_ || (v[q] == bv_ && id[q] < bi)) { bv_ = v[q]; bi = id[q]; }
        float m1v = bv_; int m1i = bi;
        #pragma unroll
        for (int o = 16; o; o >>= 1) {
            float ov = __shfl_xor_sync(0xffffffffu, m1v, o);
            int   oi = __shfl_xor_sync(0xffffffffu, m1i, o);
            if (ov > m1v || (ov == m1v && oi < m1i)) { m1v = ov; m1i = oi; }
        }
        bv_ = -3.4e38f; bi = 0x7fffffff;
        #pragma unroll
        for (int q = 0; q < 4; ++q)
            if (id[q] != m1i && (v[q] > bv_ || (v[q] == bv_ && id[q] < bi))) { bv_ = v[q]; bi = id[q]; }
        float m2v = bv_; int m2i = bi;
        #pragma unroll
        for (int o = 16; o; o >>= 1) {
            float ov = __shfl_xor_sync(0xffffffffu, m2v, o);
            int   oi = __shfl_xor_sync(0xffffffffu, m2i, o);
            if (ov > m2v || (ov == m2v && oi < m2i)) { m2v = ov; m2i = oi; }
        }
        if (lane == 0) {
            int tok = tok0 + t;
            int p0 = atomicAdd(&g_cnt[m1i], 1);
            g_list[m1i][p0] = tok * 2 + 0;
            int p1 = atomicAdd(&g_cnt[m2i], 1);
            g_list[m2i][p1] = tok * 2 + 1;
        }
    }
}

// ---------------- kernel 1.5: build balanced work queue ----------------
__global__ void scan_kernel() {
    __shared__ int ws[4];
    int e = threadIdx.x;               // 128 threads
    int c = (2 * g_cnt[e] + MC - 1) / MC;
    int lane = e & 31, w = e >> 5;
    int v = c;
    #pragma unroll
    for (int o = 1; o < 32; o <<= 1) {
        int t = __shfl_up_sync(0xffffffffu, v, o);
        if (lane >= o) v += t;
    }
    if (lane == 31) ws[w] = v;
    __syncthreads();
    int add = 0;
    for (int i = 0; i < w; ++i) add += ws[i];
    int excl = add + v - c;
    for (int i = 0; i < c; ++i)
        g_work[excl + i] = e | (i << 16);
    if (e == NE - 1) g_nwork = excl + c;
}

// ---------------- kernel 2: grouped GEMM via bf16-split HMMA ------------
// CTA (wi, nt): 32 gathered rows x 128 n-cols x K=512.
// W and x split into bf16 hi+lo planes in smem; products hh + hl + lh give
// ~fp32 accuracy. Frags fed by ldmatrix (conflict-free, PITCH = 36 u32).
// NOTE: uncapped launch bounds — the (256,4) regs=64 cap cost ILP and
// regressed the GEMM 69->81us; regs=77 @ 3 CTAs/SM is faster.
__global__ __launch_bounds__(256) void expert_gemm_kernel(
    const float* __restrict__ x_l, const float* __restrict__ x_r,
    const float* __restrict__ eW,  const float* __restrict__ eB)
{
    __shared__ unsigned Whi[BN * PITCH];   // 18.4 KB each
    __shared__ unsigned Wlo[BN * PITCH];
    __shared__ unsigned Xhi[MC * PITCH];   // 4.6 KB each
    __shared__ unsigned Xlo[MC * PITCH];

    int wi = blockIdx.x;
    if (wi >= g_nwork) return;
    int item = g_work[wi];
    int e  = item & 0xffff;
    int mp = (item >> 16) * MC;
    int nt = blockIdx.y;
    int cnt = g_cnt[e];
    int rows = 2 * cnt;

    int tid = threadIdx.x, lane = tid & 31, warp = tid >> 5;
    int mhalf = (warp & 1) * 16;       // warp's 16-row half
    int ng    = (warp >> 1) * 32;      // warp's 32-col group
    int N0    = nt * BN;
    const float* We = eW + (size_t)e * TD * TD + (size_t)N0 * TD;

    int g  = lane >> 2;                // accum row group 0..7
    int t2 = (lane & 3) * 2;           // accum col pair

    // bias (per n-tile float2)
    float2 bv[4];
    #pragma unroll
    for (int q = 0; q < 4; ++q)
        bv[q] = *reinterpret_cast<const float2*>(eB + (size_t)e * TD + N0 + ng + q * 8 + t2);

    // row metadata for this thread's 2 output rows
    int tokr[2], dsel[2], valr[2];
    #pragma unroll
    for (int i = 0; i < 2; ++i) {
        int r = mp + mhalf + g + i * 8;
        valr[i] = (r < rows);
        int rr = valr[i] ? r : 0;
        int entry = (rr < cnt) ? rr : rr - cnt;
        int str = (rr < cnt) ? 0 : 1;
        int packed = g_list[e][entry];
        tokr[i] = packed >> 1;
        dsel[i] = (packed & 1) * 2 + str;
    }

    // x loader (row xm of slice, 8 k per thread)
    int xm = tid >> 3, xk8 = (tid & 7) * 8;
    const float* xsrc = nullptr;
    {
        int lr = mp + xm;
        if (lr < rows) {
            int entry = (lr < cnt) ? lr : lr - cnt;
            const float* base = (lr < cnt) ? x_l : x_r;
            xsrc = base + (size_t)(g_list[e][entry] >> 1) * TD;
        }
    }
    // W loader (rows wn+16i, 4 k per float4)
    int wn = tid >> 4, wk4 = (tid & 15) * 4;

    float acc[4][4];
    #pragma unroll
    for (int q = 0; q < 4; ++q)
        #pragma unroll
        for (int i = 0; i < 4; ++i) acc[q][i] = 0.f;

    // ldmatrix lane offsets (u32 units)
    unsigned aOffU  = (unsigned)((mhalf + (lane & 15)) * PITCH + ((lane >> 4) & 1) * 4);
    unsigned brow   = (unsigned)(ng + ((lane >> 4) & 1) * 8 + (lane & 7));
    unsigned bkU    = (unsigned)(((lane >> 3) & 1) * 4);
    unsigned bOffU0 = brow * PITCH + bkU;
    unsigned bOffU1 = (brow + 16) * PITCH + bkU;

    unsigned XhiA = s2u(Xhi), XloA = s2u(Xlo), WhiA = s2u(Whi), WloA = s2u(Wlo);

    for (int kt = 0; kt < NKT; ++kt) {
        int k0 = kt * KC;
        __syncthreads();
        // ---- stage W tile as bf16 hi/lo planes ----
        #pragma unroll
        for (int i = 0; i < 8; ++i) {
            int n = wn + 16 * i;
            float4 v = *reinterpret_cast<const float4*>(We + (size_t)n * TD + k0 + wk4);
            unsigned h0, l0, h1, l1;
            split2(v.x, v.y, h0, l0);
            split2(v.z, v.w, h1, l1);
            int u = n * PITCH + (wk4 >> 1);
            *reinterpret_cast<uint2*>(&Whi[u]) = make_uint2(h0, h1);
            *reinterpret_cast<uint2*>(&Wlo[u]) = make_uint2(l0, l1);
        }
        // ---- stage x tile ----
        #pragma unroll
        for (int i = 0; i < 2; ++i) {
            float4 v = xsrc ? *reinterpret_cast<const float4*>(xsrc + k0 + xk8 + i * 4)
                            : make_float4(0.f, 0.f, 0.f, 0.f);
            unsigned h0, l0, h1, l1;
            split2(v.x, v.y, h0, l0);
            split2(v.z, v.w, h1, l1);
            int u = xm * PITCH + ((xk8 + i * 4) >> 1);
            *reinterpret_cast<uint2*>(&Xhi[u]) = make_uint2(h0, h1);
            *reinterpret_cast<uint2*>(&Xlo[u]) = make_uint2(l0, l1);
        }
        __syncthreads();
        // ---- 4 k16-chunks: ldmatrix + 12 HMMA each ----
        #pragma unroll
        for (int c = 0; c < 4; ++c) {
            unsigned cu4 = (unsigned)(c * 8) * 4u;   // byte offset of chunk
            unsigned ahi[4], alo[4], b0h[4], b1h[4], b0l[4], b1l[4];
            ldsm4(ahi, XhiA + (aOffU * 4u) + cu4);
            ldsm4(alo, XloA + (aOffU * 4u) + cu4);
            ldsm4(b0h, WhiA + (bOffU0 * 4u) + cu4);
            ldsm4(b1h, WhiA + (bOffU1 * 4u) + cu4);
            ldsm4(b0l, WloA + (bOffU0 * 4u) + cu4);
            ldsm4(b1l, WloA + (bOffU1 * 4u) + cu4);
            // n-tiles 0..3: (b0h[0:2], b0h[2:4], b1h[0:2], b1h[2:4])
            mma16816(acc[0], ahi, b0h + 0);
            mma16816(acc[1], ahi, b0h + 2);
            mma16816(acc[2], ahi, b1h + 0);
            mma16816(acc[3], ahi, b1h + 2);
            mma16816(acc[0], ahi, b0l + 0);
            mma16816(acc[1], ahi, b0l + 2);
            mma16816(acc[2], ahi, b1l + 0);
            mma16816(acc[3], ahi, b1l + 2);
            mma16816(acc[0], alo, b0h + 0);
            mma16816(acc[1], alo, b0h + 2);
            mma16816(acc[2], alo, b1h + 0);
            mma16816(acc[3], alo, b1h + 2);
        }
    }

    // ---- epilogue: float2 STG per (row, n-tile) ----
    #pragma unroll
    for (int q = 0; q < 4; ++q) {
        int n = N0 + ng + q * 8 + t2;
        if (valr[0]) {
            float2 o = make_float2(acc[q][0] + bv[q].x, acc[q][1] + bv[q].y);
            *reinterpret_cast<float2*>(&g_part[dsel[0]][tokr[0]][n]) = o;
        }
        if (valr[1]) {
            float2 o = make_float2(acc[q][2] + bv[q].x, acc[q][3] + bv[q].y);
            *reinterpret_cast<float2*>(&g_part[dsel[1]][tokr[1]][n]) = o;
        }
    }
}

// ---------------- kernel 3: combine slots + LayerNorm + residual --------
__global__ __launch_bounds__(128) void ln_kernel(
    const float* __restrict__ x_l, const float* __restrict__ x_r,
    const float* __restrict__ lw_l, const float* __restrict__ lb_l,
    const float* __restrict__ lw_r, const float* __restrict__ lb_r,
    float* __restrict__ out)
{
    __shared__ float red[8];
    int bid = blockIdx.x;
    int stream = bid >> 10;            // NTOK = 1024
    int tok = bid & (NTOK - 1);
    int tid = threadIdx.x;

    const float* p0 = g_part[0 * 2 + stream][tok];
    const float* p1 = g_part[1 * 2 + stream][tok];
    const float* xr = (stream ? x_r : x_l) + (size_t)tok * TD;
    const float* w  = stream ? lw_r : lw_l;
    const float* b  = stream ? lb_r : lb_l;

    int base = tid * 4;
    float4 a = *reinterpret_cast<const float4*>(p0 + base);
    float4 c = *reinterpret_cast<const float4*>(p1 + base);
    float v0 = a.x + c.x, v1 = a.y + c.y, v2 = a.z + c.z, v3 = a.w + c.w;
    float s1 = v0 + v1 + v2 + v3;
    float s2 = v0 * v0 + v1 * v1 + v2 * v2 + v3 * v3;
    #pragma unroll
    for (int o = 16; o; o >>= 1) {
        s1 += __shfl_xor_sync(0xffffffffu, s1, o);
        s2 += __shfl_xor_sync(0xffffffffu, s2, o);
    }
    int warp = tid >> 5, lane = tid & 31;
    if (lane == 0) { red[warp] = s1; red[4 + warp] = s2; }
    __syncthreads();
    float S1 = red[0] + red[1] + red[2] + red[3];
    float S2 = red[4] + red[5] + red[6] + red[7];
    float mu  = S1 * (1.f / TD);
    float var = S2 * (1.f / TD) - mu * mu;
    float rs  = rsqrtf(fmaxf(var, 0.f) + 1e-5f);

    float4 wv = *reinterpret_cast<const float4*>(w + base);
    float4 bv = *reinterpret_cast<const float4*>(b + base);
    float4 xv = *reinterpret_cast<const float4*>(xr + base);
    float4 o;
    o.x = (v0 - mu) * rs * wv.x + bv.x + xv.x;
    o.y = (v1 - mu) * rs * wv.y + bv.y + xv.y;
    o.z = (v2 - mu) * rs * wv.z + bv.z + xv.z;
    o.w = (v3 - mu) * rs * wv.w + bv.w + xv.w;
    *reinterpret_cast<float4*>(out + (size_t)stream * NTOK * TD + (size_t)tok * TD + base) = o;
}

// ---------------- launch ----------------
extern "C" void kernel_launch(void* const* d_in, const int* in_sizes, int n_in,
                              void* d_out, int out_size)
{
    const float* x_l   = (const float*)d_in[0];
    const float* x_r   = (const float*)d_in[1];
    const float* cent  = (const float*)d_in[2];
    const float* projW = (const float*)d_in[3];
    const float* projb = (const float*)d_in[4];
    const float* eW    = (const float*)d_in[5];
    const float* eB    = (const float*)d_in[6];
    const float* lwl   = (const float*)d_in[7];
    const float* lbl   = (const float*)d_in[8];
    const float* lwr   = (const float*)d_in[9];
    const float* lbr   = (const float*)d_in[10];
    float* out = (float*)d_out;

    zero_cnt_kernel<<<1, NE>>>();
    proj_kernel<<<NTOK / 128, 256>>>(x_l, x_r, projW, projb);
    score_kernel<<<NTOK / TPC, 256>>>(cent);
    scan_kernel<<<1, NE>>>();
    dim3 g(192, NT);
    expert_gemm_kernel<<<g, 256>>>(x_l, x_r, eW, eB);
    ln_kernel<<<2 * NTOK, 128>>>(x_l, x_r, lwl, lbl, lwr, lbr, out);
}

// round 17
// speedup vs baseline: 1.4729x; 1.4729x over previous
#include <cuda_runtime.h>
#include <cuda_bf16.h>

// ---------------- problem constants ----------------
#define BSZ   8
#define NC    128
#define TD    512
#define EDIM  64
#define NE    128
#define NTOK  (BSZ*NC)     // 1024 tokens
#define T2    (2*TD)       // 1024 concat dim

// ---------------- GEMM tiling ----------------
#define BN 128             // n-columns per CTA
#define NT (TD/BN)         // 4 n-tiles
#define KC 64              // k-tile
#define MC 32              // m rows per work item
#define NKT (TD/KC)        // 8 k-tiles
#define PITCH 36           // smem row pitch in u32 units (32 data + 4 pad)
#define APITCH 20          // proj kernel pitch (16 data u32 + 4 pad)
#define MAXW 256           // max work items
#define KSL 8              // proj k-slices

// ---------------- device scratch (no allocation allowed) ----------------
__device__ int   g_cnt[NE];
__device__ int   g_list[NE][NTOK];          // packed token*2 + slot
__device__ int   g_work[MAXW];              // expert | (m-slice << 16)
__device__ int   g_nwork;
__device__ float g_psp[KSL][NTOK][EDIM];    // proj partials (2 MB)
__device__ float g_part[4][NTOK][TD];       // [slot*2+stream][token][t]  (8 MB)

// ---------------- helpers ----------------
__device__ __forceinline__ unsigned s2u(const void* p) {
    return (unsigned)__cvta_generic_to_shared(p);
}
__device__ __forceinline__ void ldsm4(unsigned* r, unsigned addr) {
    asm volatile("ldmatrix.sync.aligned.m8n8.x4.shared.b16 {%0,%1,%2,%3},[%4];"
                 : "=r"(r[0]), "=r"(r[1]), "=r"(r[2]), "=r"(r[3]) : "r"(addr));
}
__device__ __forceinline__ void mma16816(float* d, const unsigned* a, const unsigned* b) {
    asm volatile("mma.sync.aligned.m16n8k16.row.col.f32.bf16.bf16.f32 "
                 "{%0,%1,%2,%3},{%4,%5,%6,%7},{%8,%9},{%0,%1,%2,%3};"
                 : "+f"(d[0]), "+f"(d[1]), "+f"(d[2]), "+f"(d[3])
                 : "r"(a[0]), "r"(a[1]), "r"(a[2]), "r"(a[3]), "r"(b[0]), "r"(b[1]));
}
// split fp32 pair -> packed bf16x2 hi + lo (2-term expansion)
__device__ __forceinline__ void split2(float v0, float v1, unsigned& h, unsigned& l) {
    __nv_bfloat162 hb;
    hb.x = __float2bfloat16(v0);
    hb.y = __float2bfloat16(v1);
    h = *reinterpret_cast<unsigned*>(&hb);
    float r0 = v0 - __bfloat162float(hb.x);
    float r1 = v1 - __bfloat162float(hb.y);
    __nv_bfloat162 lb;
    lb.x = __float2bfloat16(r0);
    lb.y = __float2bfloat16(r1);
    l = *reinterpret_cast<unsigned*>(&lb);
}

// ---------------- kernel 0: zero per-expert counters ----------------
__global__ void zero_cnt_kernel() { g_cnt[threadIdx.x] = 0; }

// ---------------- kernel 1a: router projection, partial HMMA GEMM -------
// CTA (token-tile bx, k-slice by): g_psp[by][tok][j] = partial dot over
// k in [by*128, by*128+128). 4-term bf16 split -> score error ~1e-7.
// Loaders are COALESCED (lanes along k, nL=4) — the R16 version had lanes
// across rows (nL=32) and only 8 CTAs; both fixed here.
__global__ __launch_bounds__(256) void proj_kernel(
    const float* __restrict__ x_l, const float* __restrict__ x_r,
    const float* __restrict__ projW)
{
    __shared__ unsigned Phi[64 * APITCH], Plo[64 * APITCH];    // 5.1 KB each
    __shared__ unsigned Ahi[128 * APITCH], Alo[128 * APITCH];  // 10.2 KB each

    int tid = threadIdx.x, lane = tid & 31, warp = tid >> 5;
    int tok0 = blockIdx.x * 128;
    int ks0  = blockIdx.y * 128;                // k-slice base (global concat k)
    // whole slice is in one stream (128 | 512): uniform select
    const float* xbase = (ks0 < TD) ? x_l : x_r;
    int kloc0 = (ks0 < TD) ? ks0 : ks0 - TD;

    // coalesced loader mapping: 8 lanes along k (32 floats), rows = tid>>3
    int kx4  = (tid & 7) * 4;                   // 0..28
    int lrow = tid >> 3;                        // 0..31

    float acc[8][4];
    #pragma unroll
    for (int q = 0; q < 8; ++q)
        #pragma unroll
        for (int i = 0; i < 4; ++i) acc[q][i] = 0.f;

    unsigned aOffU = (unsigned)((warp * 16 + (lane & 15)) * APITCH + ((lane >> 4) & 1) * 4);
    unsigned brow0 = (unsigned)(((lane >> 4) & 1) * 8 + (lane & 7));
    unsigned bkU   = (unsigned)(((lane >> 3) & 1) * 4);
    unsigned bOff[4];
    #pragma unroll
    for (int gg = 0; gg < 4; ++gg) bOff[gg] = (brow0 + 16 * gg) * APITCH + bkU;

    unsigned AhiA = s2u(Ahi), AloA = s2u(Alo), PhiA = s2u(Phi), PloA = s2u(Plo);

    for (int kt = 0; kt < 4; ++kt) {            // 4 k-tiles of 32 per slice
        int k0 = kt * 32;
        __syncthreads();
        // ---- projW tile: rows lrow, lrow+32 (coalesced LDG.128) ----
        #pragma unroll
        for (int i = 0; i < 2; ++i) {
            int r = lrow + 32 * i;
            float4 v = *reinterpret_cast<const float4*>(
                projW + (size_t)r * T2 + ks0 + k0 + kx4);
            unsigned h0, l0, h1, l1;
            split2(v.x, v.y, h0, l0);
            split2(v.z, v.w, h1, l1);
            int u = r * APITCH + (kx4 >> 1);
            *reinterpret_cast<uint2*>(&Phi[u]) = make_uint2(h0, h1);
            *reinterpret_cast<uint2*>(&Plo[u]) = make_uint2(l0, l1);
        }
        // ---- x tile: rows lrow + 32i, i=0..3 (coalesced) ----
        #pragma unroll
        for (int i = 0; i < 4; ++i) {
            int r = lrow + 32 * i;
            float4 v = *reinterpret_cast<const float4*>(
                xbase + (size_t)(tok0 + r) * TD + kloc0 + k0 + kx4);
            unsigned h0, l0, h1, l1;
            split2(v.x, v.y, h0, l0);
            split2(v.z, v.w, h1, l1);
            int u = r * APITCH + (kx4 >> 1);
            *reinterpret_cast<uint2*>(&Ahi[u]) = make_uint2(h0, h1);
            *reinterpret_cast<uint2*>(&Alo[u]) = make_uint2(l0, l1);
        }
        __syncthreads();
        // ---- 2 k16-chunks ----
        #pragma unroll
        for (int c = 0; c < 2; ++c) {
            unsigned cu4 = (unsigned)(c * 8) * 4u;
            unsigned ahi[4], alo[4], bh[4][4], bl[4][4];
            ldsm4(ahi, AhiA + aOffU * 4u + cu4);
            ldsm4(alo, AloA + aOffU * 4u + cu4);
            #pragma unroll
            for (int gg = 0; gg < 4; ++gg) {
                ldsm4(bh[gg], PhiA + bOff[gg] * 4u + cu4);
                ldsm4(bl[gg], PloA + bOff[gg] * 4u + cu4);
            }
            #pragma unroll
            for (int gg = 0; gg < 4; ++gg) {
                mma16816(acc[2 * gg],     ahi, bh[gg] + 0);
                mma16816(acc[2 * gg + 1], ahi, bh[gg] + 2);
                mma16816(acc[2 * gg],     ahi, bl[gg] + 0);
                mma16816(acc[2 * gg + 1], ahi, bl[gg] + 2);
                mma16816(acc[2 * gg],     alo, bh[gg] + 0);
                mma16816(acc[2 * gg + 1], alo, bh[gg] + 2);
                mma16816(acc[2 * gg],     alo, bl[gg] + 0);
                mma16816(acc[2 * gg + 1], alo, bl[gg] + 2);
            }
        }
    }

    // epilogue: partial sums (bias added in score_kernel)
    int ksl = blockIdx.y;
    int r0 = tok0 + warp * 16 + (lane >> 2);
    int c0 = (lane & 3) * 2;
    #pragma unroll
    for (int q = 0; q < 8; ++q) {
        int col = q * 8 + c0;
        *reinterpret_cast<float2*>(&g_psp[ksl][r0][col]) =
            make_float2(acc[q][0], acc[q][1]);
        *reinterpret_cast<float2*>(&g_psp[ksl][r0 + 8][col]) =
            make_float2(acc[q][2], acc[q][3]);
    }
}

// ---------------- kernel 1b: reduce partials + scores + top-2 ----------
// s_e = ps . centers[e]/||centers[e]||; x_proj L2-norm is a positive
// per-token scalar (order-preserving) and the reference's token-level mask
// makes each selected expert's combine weight exactly 1.0.
#define TPC 8
__global__ __launch_bounds__(256) void score_kernel(
    const float* __restrict__ centers, const float* __restrict__ projb)
{
    __shared__ float ps[TPC][EDIM];    // 2 KB
    __shared__ float ss[TPC][NE];      // 4 KB
    int tok0 = blockIdx.x * TPC;
    int tid = threadIdx.x;
    int warp = tid >> 5, lane = tid & 31;

    // reduce 8 k-slice partials + bias
    #pragma unroll
    for (int i = tid; i < TPC * EDIM; i += 256) {
        int t = i >> 6, j = i & 63;
        float s = projb[j];
        #pragma unroll
        for (int sl = 0; sl < KSL; ++sl) s += g_psp[sl][tok0 + t][j];
        ps[t][j] = s;
    }
    __syncthreads();

    // 1024 (token, expert) scores over 256 threads, 4 rounds
    #pragma unroll
    for (int r = 0; r < 4; ++r) {
        int idx = tid + 256 * r;
        int t = idx >> 7, e = idx & 127;
        const float* c = centers + (size_t)e * EDIM;
        float s = 0.f, n = 0.f;
        #pragma unroll 8
        for (int j = 0; j < EDIM; ++j) { float cv = c[j]; s += ps[t][j] * cv; n += cv * cv; }
        ss[t][e] = s * rsqrtf(fmaxf(n, 1e-24f));
    }
    __syncthreads();

    // warp-parallel top-2: warp t reduces token t's 128 scores.
    // tie-break: smaller index wins (matches jax.lax.top_k first-index).
    {
        int t = warp;
        float v[4]; int id[4];
        #pragma unroll
        for (int q = 0; q < 4; ++q) { id[q] = lane + 32 * q; v[q] = ss[t][id[q]]; }
        float bv_ = v[0]; int bi = id[0];
        #pragma unroll
        for (int q = 1; q < 4; ++q)
            if (v[q] > bv_ || (v[q] == bv_ && id[q] < bi)) { bv_ = v[q]; bi = id[q]; }
        float m1v = bv_; int m1i = bi;
        #pragma unroll
        for (int o = 16; o; o >>= 1) {
            float ov = __shfl_xor_sync(0xffffffffu, m1v, o);
            int   oi = __shfl_xor_sync(0xffffffffu, m1i, o);
            if (ov > m1v || (ov == m1v && oi < m1i)) { m1v = ov; m1i = oi; }
        }
        bv_ = -3.4e38f; bi = 0x7fffffff;
        #pragma unroll
        for (int q = 0; q < 4; ++q)
            if (id[q] != m1i && (v[q] > bv_ || (v[q] == bv_ && id[q] < bi))) { bv_ = v[q]; bi = id[q]; }
        float m2v = bv_; int m2i = bi;
        #pragma unroll
        for (int o = 16; o; o >>= 1) {
            float ov = __shfl_xor_sync(0xffffffffu, m2v, o);
            int   oi = __shfl_xor_sync(0xffffffffu, m2i, o);
            if (ov > m2v || (ov == m2v && oi < m2i)) { m2v = ov; m2i = oi; }
        }
        if (lane == 0) {
            int tok = tok0 + t;
            int p0 = atomicAdd(&g_cnt[m1i], 1);
            g_list[m1i][p0] = tok * 2 + 0;
            int p1 = atomicAdd(&g_cnt[m2i], 1);
            g_list[m2i][p1] = tok * 2 + 1;
        }
    }
}

// ---------------- kernel 1.5: build balanced work queue ----------------
__global__ void scan_kernel() {
    __shared__ int ws[4];
    int e = threadIdx.x;               // 128 threads
    int c = (2 * g_cnt[e] + MC - 1) / MC;
    int lane = e & 31, w = e >> 5;
    int v = c;
    #pragma unroll
    for (int o = 1; o < 32; o <<= 1) {
        int t = __shfl_up_sync(0xffffffffu, v, o);
        if (lane >= o) v += t;
    }
    if (lane == 31) ws[w] = v;
    __syncthreads();
    int add = 0;
    for (int i = 0; i < w; ++i) add += ws[i];
    int excl = add + v - c;
    for (int i = 0; i < c; ++i)
        g_work[excl + i] = e | (i << 16);
    if (e == NE - 1) g_nwork = excl + c;
}

// ---------------- kernel 2: grouped GEMM via bf16-split HMMA ------------
// CTA (wi, nt): 32 gathered rows x 128 n-cols x K=512.
// W and x split into bf16 hi+lo planes in smem; products hh + hl + lh give
// ~fp32 accuracy. Frags fed by ldmatrix (conflict-free, PITCH = 36 u32).
// NOTE: uncapped launch bounds — the (256,4) regs=64 cap cost ILP and
// regressed the GEMM 69->81us; regs=77 @ 3 CTAs/SM is faster.
__global__ __launch_bounds__(256) void expert_gemm_kernel(
    const float* __restrict__ x_l, const float* __restrict__ x_r,
    const float* __restrict__ eW,  const float* __restrict__ eB)
{
    __shared__ unsigned Whi[BN * PITCH];   // 18.4 KB each
    __shared__ unsigned Wlo[BN * PITCH];
    __shared__ unsigned Xhi[MC * PITCH];   // 4.6 KB each
    __shared__ unsigned Xlo[MC * PITCH];

    int wi = blockIdx.x;
    if (wi >= g_nwork) return;
    int item = g_work[wi];
    int e  = item & 0xffff;
    int mp = (item >> 16) * MC;
    int nt = blockIdx.y;
    int cnt = g_cnt[e];
    int rows = 2 * cnt;

    int tid = threadIdx.x, lane = tid & 31, warp = tid >> 5;
    int mhalf = (warp & 1) * 16;       // warp's 16-row half
    int ng    = (warp >> 1) * 32;      // warp's 32-col group
    int N0    = nt * BN;
    const float* We = eW + (size_t)e * TD * TD + (size_t)N0 * TD;

    int g  = lane >> 2;                // accum row group 0..7
    int t2 = (lane & 3) * 2;           // accum col pair

    // bias (per n-tile float2)
    float2 bv[4];
    #pragma unroll
    for (int q = 0; q < 4; ++q)
        bv[q] = *reinterpret_cast<const float2*>(eB + (size_t)e * TD + N0 + ng + q * 8 + t2);

    // row metadata for this thread's 2 output rows
    int tokr[2], dsel[2], valr[2];
    #pragma unroll
    for (int i = 0; i < 2; ++i) {
        int r = mp + mhalf + g + i * 8;
        valr[i] = (r < rows);
        int rr = valr[i] ? r : 0;
        int entry = (rr < cnt) ? rr : rr - cnt;
        int str = (rr < cnt) ? 0 : 1;
        int packed = g_list[e][entry];
        tokr[i] = packed >> 1;
        dsel[i] = (packed & 1) * 2 + str;
    }

    // x loader (row xm of slice, 8 k per thread)
    int xm = tid >> 3, xk8 = (tid & 7) * 8;
    const float* xsrc = nullptr;
    {
        int lr = mp + xm;
        if (lr < rows) {
            int entry = (lr < cnt) ? lr : lr - cnt;
            const float* base = (lr < cnt) ? x_l : x_r;
            xsrc = base + (size_t)(g_list[e][entry] >> 1) * TD;
        }
    }
    // W loader (rows wn+16i, 4 k per float4)
    int wn = tid >> 4, wk4 = (tid & 15) * 4;

    float acc[4][4];
    #pragma unroll
    for (int q = 0; q < 4; ++q)
        #pragma unroll
        for (int i = 0; i < 4; ++i) acc[q][i] = 0.f;

    // ldmatrix lane offsets (u32 units)
    unsigned aOffU  = (unsigned)((mhalf + (lane & 15)) * PITCH + ((lane >> 4) & 1) * 4);
    unsigned brow   = (unsigned)(ng + ((lane >> 4) & 1) * 8 + (lane & 7));
    unsigned bkU    = (unsigned)(((lane >> 3) & 1) * 4);
    unsigned bOffU0 = brow * PITCH + bkU;
    unsigned bOffU1 = (brow + 16) * PITCH + bkU;

    unsigned XhiA = s2u(Xhi), XloA = s2u(Xlo), WhiA = s2u(Whi), WloA = s2u(Wlo);

    for (int kt = 0; kt < NKT; ++kt) {
        int k0 = kt * KC;
        __syncthreads();
        // ---- stage W tile as bf16 hi/lo planes ----
        #pragma unroll
        for (int i = 0; i < 8; ++i) {
            int n = wn + 16 * i;
            float4 v = *reinterpret_cast<const float4*>(We + (size_t)n * TD + k0 + wk4);
            unsigned h0, l0, h1, l1;
            split2(v.x, v.y, h0, l0);
            split2(v.z, v.w, h1, l1);
            int u = n * PITCH + (wk4 >> 1);
            *reinterpret_cast<uint2*>(&Whi[u]) = make_uint2(h0, h1);
            *reinterpret_cast<uint2*>(&Wlo[u]) = make_uint2(l0, l1);
        }
        // ---- stage x tile ----
        #pragma unroll
        for (int i = 0; i < 2; ++i) {
            float4 v = xsrc ? *reinterpret_cast<const float4*>(xsrc + k0 + xk8 + i * 4)
                            : make_float4(0.f, 0.f, 0.f, 0.f);
            unsigned h0, l0, h1, l1;
            split2(v.x, v.y, h0, l0);
            split2(v.z, v.w, h1, l1);
            int u = xm * PITCH + ((xk8 + i * 4) >> 1);
            *reinterpret_cast<uint2*>(&Xhi[u]) = make_uint2(h0, h1);
            *reinterpret_cast<uint2*>(&Xlo[u]) = make_uint2(l0, l1);
        }
        __syncthreads();
        // ---- 4 k16-chunks: ldmatrix + 12 HMMA each ----
        #pragma unroll
        for (int c = 0; c < 4; ++c) {
            unsigned cu4 = (unsigned)(c * 8) * 4u;   // byte offset of chunk
            unsigned ahi[4], alo[4], b0h[4], b1h[4], b0l[4], b1l[4];
            ldsm4(ahi, XhiA + (aOffU * 4u) + cu4);
            ldsm4(alo, XloA + (aOffU * 4u) + cu4);
            ldsm4(b0h, WhiA + (bOffU0 * 4u) + cu4);
            ldsm4(b1h, WhiA + (bOffU1 * 4u) + cu4);
            ldsm4(b0l, WloA + (bOffU0 * 4u) + cu4);
            ldsm4(b1l, WloA + (bOffU1 * 4u) + cu4);
            // n-tiles 0..3: (b0h[0:2], b0h[2:4], b1h[0:2], b1h[2:4])
            mma16816(acc[0], ahi, b0h + 0);
            mma16816(acc[1], ahi, b0h + 2);
            mma16816(acc[2], ahi, b1h + 0);
            mma16816(acc[3], ahi, b1h + 2);
            mma16816(acc[0], ahi, b0l + 0);
            mma16816(acc[1], ahi, b0l + 2);
            mma16816(acc[2], ahi, b1l + 0);
            mma16816(acc[3], ahi, b1l + 2);
            mma16816(acc[0], alo, b0h + 0);
            mma16816(acc[1], alo, b0h + 2);
            mma16816(acc[2], alo, b1h + 0);
            mma16816(acc[3], alo, b1h + 2);
        }
    }

    // ---- epilogue: float2 STG per (row, n-tile) ----
    #pragma unroll
    for (int q = 0; q < 4; ++q) {
        int n = N0 + ng + q * 8 + t2;
        if (valr[0]) {
            float2 o = make_float2(acc[q][0] + bv[q].x, acc[q][1] + bv[q].y);
            *reinterpret_cast<float2*>(&g_part[dsel[0]][tokr[0]][n]) = o;
        }
        if (valr[1]) {
            float2 o = make_float2(acc[q][2] + bv[q].x, acc[q][3] + bv[q].y);
            *reinterpret_cast<float2*>(&g_part[dsel[1]][tokr[1]][n]) = o;
        }
    }
}

// ---------------- kernel 3: combine slots + LayerNorm + residual --------
__global__ __launch_bounds__(128) void ln_kernel(
    const float* __restrict__ x_l, const float* __restrict__ x_r,
    const float* __restrict__ lw_l, const float* __restrict__ lb_l,
    const float* __restrict__ lw_r, const float* __restrict__ lb_r,
    float* __restrict__ out)
{
    __shared__ float red[8];
    int bid = blockIdx.x;
    int stream = bid >> 10;            // NTOK = 1024
    int tok = bid & (NTOK - 1);
    int tid = threadIdx.x;

    const float* p0 = g_part[0 * 2 + stream][tok];
    const float* p1 = g_part[1 * 2 + stream][tok];
    const float* xr = (stream ? x_r : x_l) + (size_t)tok * TD;
    const float* w  = stream ? lw_r : lw_l;
    const float* b  = stream ? lb_r : lb_l;

    int base = tid * 4;
    float4 a = *reinterpret_cast<const float4*>(p0 + base);
    float4 c = *reinterpret_cast<const float4*>(p1 + base);
    float v0 = a.x + c.x, v1 = a.y + c.y, v2 = a.z + c.z, v3 = a.w + c.w;
    float s1 = v0 + v1 + v2 + v3;
    float s2 = v0 * v0 + v1 * v1 + v2 * v2 + v3 * v3;
    #pragma unroll
    for (int o = 16; o; o >>= 1) {
        s1 += __shfl_xor_sync(0xffffffffu, s1, o);
        s2 += __shfl_xor_sync(0xffffffffu, s2, o);
    }
    int warp = tid >> 5, lane = tid & 31;
    if (lane == 0) { red[warp] = s1; red[4 + warp] = s2; }
    __syncthreads();
    float S1 = red[0] + red[1] + red[2] + red[3];
    float S2 = red[4] + red[5] + red[6] + red[7];
    float mu  = S1 * (1.f / TD);
    float var = S2 * (1.f / TD) - mu * mu;
    float rs  = rsqrtf(fmaxf(var, 0.f) + 1e-5f);

    float4 wv = *reinterpret_cast<const float4*>(w + base);
    float4 bv = *reinterpret_cast<const float4*>(b + base);
    float4 xv = *reinterpret_cast<const float4*>(xr + base);
    float4 o;
    o.x = (v0 - mu) * rs * wv.x + bv.x + xv.x;
    o.y = (v1 - mu) * rs * wv.y + bv.y + xv.y;
    o.z = (v2 - mu) * rs * wv.z + bv.z + xv.z;
    o.w = (v3 - mu) * rs * wv.w + bv.w + xv.w;
    *reinterpret_cast<float4*>(out + (size_t)stream * NTOK * TD + (size_t)tok * TD + base) = o;
}

// ---------------- launch ----------------
extern "C" void kernel_launch(void* const* d_in, const int* in_sizes, int n_in,
                              void* d_out, int out_size)
{
    const float* x_l   = (const float*)d_in[0];
    const float* x_r   = (const float*)d_in[1];
    const float* cent  = (const float*)d_in[2];
    const float* projW = (const float*)d_in[3];
    const float* projb = (const float*)d_in[4];
    const float* eW    = (const float*)d_in[5];
    const float* eB    = (const float*)d_in[6];
    const float* lwl   = (const float*)d_in[7];
    const float* lbl   = (const float*)d_in[8];
    const float* lwr   = (const float*)d_in[9];
    const float* lbr   = (const float*)d_in[10];
    float* out = (float*)d_out;

    zero_cnt_kernel<<<1, NE>>>();
    dim3 pg(NTOK / 128, KSL);
    proj_kernel<<<pg, 256>>>(x_l, x_r, projW);
    score_kernel<<<NTOK / TPC, 256>>>(cent, projb);
    scan_kernel<<<1, NE>>>();
    dim3 g(192, NT);
    expert_gemm_kernel<<<g, 256>>>(x_l, x_r, eW, eB);
    ln_kernel<<<2 * NTOK, 128>>>(x_l, x_r, lwl, lbl, lwr, lbr, out);
}